// round 1
// baseline (speedup 1.0000x reference)
#include <cuda_runtime.h>
#include <math.h>

#define N_LEVELS      16
#define N_FEATS       2
#define HASHMAP_SIZE  (1u << 19)
#define HASH_MASK     (HASHMAP_SIZE - 1u)

struct ResTable {
    int res[N_LEVELS];
};

__global__ void __launch_bounds__(256)
hashenc_kernel(const float* __restrict__ pos,
               const float* __restrict__ emb,
               float* __restrict__ out,
               ResTable rt,
               int n_points)
{
    int p = blockIdx.x * blockDim.x + threadIdx.x;
    if (p >= n_points) return;

    const float px = pos[p * 3 + 0];
    const float py = pos[p * 3 + 1];
    const float pz = pos[p * 3 + 2];

    float result[2 * N_LEVELS];

#pragma unroll
    for (int l = 0; l < N_LEVELS; ++l) {
        const int   res  = rt.res[l];
        const float fres = (float)res;

        // scaled coords, integer cell, fractional weights (float32, matching ref)
        const float sx = px * fres, sy = py * fres, sz = pz * fres;
        const float fx = floorf(sx), fy = floorf(sy), fz = floorf(sz);
        const int   vx = (int)fx,   vy = (int)fy,   vz = (int)fz;
        const float wx = sx - fx,   wy = sy - fy,   wz = sz - fz;

        const float2* __restrict__ table =
            reinterpret_cast<const float2*>(emb) + (size_t)l * HASHMAP_SIZE;

        const unsigned r1 = (unsigned)(res + 1);
        // dense iff (res+1)^3 <= 2^19  (uniform per level)
        const bool dense =
            ((long long)r1 * (long long)r1 * (long long)r1) <= (long long)HASHMAP_SIZE;

        float2 f[8];
#pragma unroll
        for (int c = 0; c < 8; ++c) {
            const int cx = vx + ((c >> 2) & 1);   // CORNER_OFFSETS: i = bit2
            const int cy = vy + ((c >> 1) & 1);   //                 j = bit1
            const int cz = vz + (c & 1);          //                 k = bit0
            unsigned idx;
            if (dense) {
                idx = (unsigned)cx * (r1 * r1) + (unsigned)cy * r1 + (unsigned)cz;
            } else {
                const unsigned h = (unsigned)cx * 1u
                                 ^ (unsigned)cy * 2654435761u
                                 ^ (unsigned)cz * 805459861u;
                idx = h & HASH_MASK;
            }
            f[c] = __ldg(&table[idx]);
        }

        const float omx = 1.0f - wx, omy = 1.0f - wy, omz = 1.0f - wz;

        // lerp along x (feat 0 and feat 1)
        float c00x = f[0].x * omx + f[4].x * wx;
        float c00y = f[0].y * omx + f[4].y * wx;
        float c01x = f[1].x * omx + f[5].x * wx;
        float c01y = f[1].y * omx + f[5].y * wx;
        float c10x = f[2].x * omx + f[6].x * wx;
        float c10y = f[2].y * omx + f[6].y * wx;
        float c11x = f[3].x * omx + f[7].x * wx;
        float c11y = f[3].y * omx + f[7].y * wx;

        // lerp along y
        float c0x = c00x * omy + c10x * wy;
        float c0y = c00y * omy + c10y * wy;
        float c1x = c01x * omy + c11x * wy;
        float c1y = c01y * omy + c11y * wy;

        // lerp along z
        result[2 * l + 0] = c0x * omz + c1x * wz;
        result[2 * l + 1] = c0y * omz + c1y * wz;
    }

    // coalesced 128-byte store per thread (8x float4)
    float4* __restrict__ o4 = reinterpret_cast<float4*>(out + (size_t)p * (2 * N_LEVELS));
#pragma unroll
    for (int i = 0; i < 8; ++i) {
        o4[i] = reinterpret_cast<const float4*>(result)[i];
    }
}

extern "C" void kernel_launch(void* const* d_in, const int* in_sizes, int n_in,
                              void* d_out, int out_size)
{
    const float* positions  = (const float*)d_in[0];   // [N_POINTS, 3] f32
    const float* embeddings = (const float*)d_in[1];   // [16, 2^19, 2] f32
    float*       out        = (float*)d_out;           // [N_POINTS, 32] f32

    const int n_points = in_sizes[0] / 3;

    // Mirror numpy exactly in double precision (libm exp/log/pow):
    //   scale = exp((log(2048) - log(16)) / 15);  res_l = floor(16 * scale**l)
    ResTable rt;
    const double scale = exp((log(2048.0) - log(16.0)) / 15.0);
    for (int l = 0; l < N_LEVELS; ++l) {
        rt.res[l] = (int)floor(16.0 * pow(scale, (double)l));
    }

    const int threads = 256;
    const int blocks  = (n_points + threads - 1) / threads;
    hashenc_kernel<<<blocks, threads>>>(positions, embeddings, out, rt, n_points);
}